// round 10
// baseline (speedup 1.0000x reference)
#include <cuda_runtime.h>
#include <math.h>

#define Sdim 2048
#define Edim 512
#define WIN  11
#define Fdim 5632            // WIN * Edim
#define NTH  256

// Packed dual-fp32 FMA: a.{x,y} += {xlo,xhi} * w   (w broadcast to both lanes)
__device__ __forceinline__ void ffma2(float2& a, float xlo, float xhi, float w) {
    asm("{\n\t.reg .b64 X, Wd, A;\n\t"
        "mov.b64 X, {%2, %3};\n\t"
        "mov.b64 Wd, {%4, %4};\n\t"
        "mov.b64 A, {%0, %1};\n\t"
        "fma.rn.f32x2 A, X, Wd, A;\n\t"
        "mov.b64 {%0, %1}, A;\n\t}"
        : "+f"(a.x), "+f"(a.y) : "f"(xlo), "f"(xhi), "f"(w));
}

__device__ __forceinline__ float tanh_fast(float v) {
    float r;
    asm("tanh.approx.f32 %0, %1;" : "=f"(r) : "f"(v));
    return r;
}

// Stage A for one w-group: ROWS window rows starting at Wg, 4 batches.
template<int ROWS>
__device__ __forceinline__ void stageA(const float* __restrict__ Wg,
                                       const float* __restrict__ xb,
                                       int s, size_t bst, float2 (&acc)[2][6]) {
    const bool interior = (s >= 5) && (s <= Sdim - 6);
    if (interior) {
        const float* xr0 = xb + (size_t)(s - 5) * Edim;
        #pragma unroll
        for (int i = 0; i < WIN; i++) {
            float4 w4[ROWS];
            #pragma unroll
            for (int r = 0; r < ROWS; r++)
                w4[r] = *(const float4*)(Wg + (size_t)r * Fdim + i * Edim);
            float4 xv0 = *(const float4*)(xr0 + i * Edim);
            float4 xv1 = *(const float4*)(xr0 + i * Edim + bst);
            float4 xv2 = *(const float4*)(xr0 + i * Edim + 2 * bst);
            float4 xv3 = *(const float4*)(xr0 + i * Edim + 3 * bst);
            #pragma unroll
            for (int r = 0; r < ROWS; r++) {
                ffma2(acc[0][r], xv0.x, xv1.x, w4[r].x);
                ffma2(acc[0][r], xv0.y, xv1.y, w4[r].y);
                ffma2(acc[0][r], xv0.z, xv1.z, w4[r].z);
                ffma2(acc[0][r], xv0.w, xv1.w, w4[r].w);
                ffma2(acc[1][r], xv2.x, xv3.x, w4[r].x);
                ffma2(acc[1][r], xv2.y, xv3.y, w4[r].y);
                ffma2(acc[1][r], xv2.z, xv3.z, w4[r].z);
                ffma2(acc[1][r], xv2.w, xv3.w, w4[r].w);
            }
        }
    } else {
        for (int i = 0; i < WIN; i++) {
            int row = s + i - 5;
            if ((unsigned)row >= (unsigned)Sdim) continue;
            float4 w4[ROWS];
            #pragma unroll
            for (int r = 0; r < ROWS; r++)
                w4[r] = *(const float4*)(Wg + (size_t)r * Fdim + i * Edim);
            const float* xr = xb + (size_t)row * Edim;
            float4 xv0 = *(const float4*)(xr);
            float4 xv1 = *(const float4*)(xr + bst);
            float4 xv2 = *(const float4*)(xr + 2 * bst);
            float4 xv3 = *(const float4*)(xr + 3 * bst);
            #pragma unroll
            for (int r = 0; r < ROWS; r++) {
                ffma2(acc[0][r], xv0.x, xv1.x, w4[r].x);
                ffma2(acc[0][r], xv0.y, xv1.y, w4[r].y);
                ffma2(acc[0][r], xv0.z, xv1.z, w4[r].z);
                ffma2(acc[0][r], xv0.w, xv1.w, w4[r].w);
                ffma2(acc[1][r], xv2.x, xv3.x, w4[r].x);
                ffma2(acc[1][r], xv2.y, xv3.y, w4[r].y);
                ffma2(acc[1][r], xv2.z, xv3.z, w4[r].z);
                ffma2(acc[1][r], xv2.w, xv3.w, w4[r].w);
            }
        }
    }
}

__global__ __launch_bounds__(NTH, 3)
void winattn_kernel(const float* __restrict__ x,
                    const float* __restrict__ W,
                    const float* __restrict__ bias,
                    float* __restrict__ out) {
    __shared__ float2 red[8][24];      // per-warp partials (2 pairs x up-to-6 rows)
    __shared__ float2 gates[22];       // gates for this CTA's 4 batches

    const int s   = blockIdx.x >> 1;
    const int b0  = (blockIdx.x & 1) * 4;   // batches b0..b0+3
    const int tid = threadIdx.x;
    const int grp = tid >> 7;               // 0: w=0..5,  1: w=6..10
    const int h   = tid & 127;
    const int ex  = 4 * h;                  // float4 slot within e

    const size_t bst = (size_t)Sdim * Edim;
    const float* Wg = W + (size_t)s * (WIN * Fdim) + (size_t)(grp * 6) * Fdim + ex;
    const float* xb = x + (size_t)b0 * bst + ex;

    // ---------------- Stage A: gate partial dots (w-split) -----------------
    float2 acc[2][6];
    #pragma unroll
    for (int p = 0; p < 2; p++)
        #pragma unroll
        for (int r = 0; r < 6; r++)
            acc[p][r] = make_float2(0.f, 0.f);

    if (grp == 0) stageA<6>(Wg, xb, s, bst, acc);
    else          stageA<5>(Wg, xb, s, bst, acc);

    // ---------------- reduce: warp shfl, 4 warps/group via smem ------------
    float* af = (float*)acc;           // 24 floats
    #pragma unroll
    for (int off = 16; off > 0; off >>= 1) {
        #pragma unroll
        for (int i = 0; i < 24; i++)
            af[i] += __shfl_xor_sync(0xffffffffu, af[i], off);
    }
    const int lane = tid & 31, wrp = tid >> 5;   // wrp 0..7, group = wrp>>2
    if (lane == 0) {
        #pragma unroll
        for (int p = 0; p < 2; p++)
            #pragma unroll
            for (int r = 0; r < 6; r++)
                red[wrp][p * 6 + r] = acc[p][r];
    }
    __syncthreads();

    if (tid < 22) {
        int p = tid / WIN;             // local pair 0..1
        int w = tid - p * WIN;
        int g2   = (w < 6) ? 0 : 1;
        int slot = p * 6 + (g2 ? (w - 6) : w);
        float2 t = make_float2(0.f, 0.f);
        #pragma unroll
        for (int q = 0; q < 4; q++) {
            float2 v = red[g2 * 4 + q][slot];
            t.x += v.x;
            t.y += v.y;
        }
        float bb = bias[s * WIN + w];
        float2 gt;
        gt.x = 1.0f / (1.0f + expf(-(t.x + bb)));
        gt.y = 1.0f / (1.0f + expf(-(t.y + bb)));
        gates[tid] = gt;               // .x = batch b0+2p, .y = batch b0+2p+1
    }
    __syncthreads();

    // ---------------- Stage B: score + tanh (2 batches per thread) ---------
    // group grp owns batches b0+2*grp, b0+2*grp+1 at float4 slot ex
    const float* xq = x + (size_t)(b0 + 2 * grp) * bst + ex;
    float2 a0[2], a1[2];
    a0[0] = a0[1] = a1[0] = a1[1] = make_float2(0.f, 0.f);

    const bool interior = (s >= 5) && (s <= Sdim - 6);
    if (interior) {
        const float* xr0 = xq + (size_t)(s - 5) * Edim;
        #pragma unroll
        for (int w = 0; w < WIN; w++) {
            float4 xv0 = *(const float4*)(xr0 + w * Edim);
            float4 xv1 = *(const float4*)(xr0 + w * Edim + bst);
            float2 g = gates[grp * WIN + w];
            ffma2(a0[0], xv0.x, xv0.y, g.x);
            ffma2(a0[1], xv0.z, xv0.w, g.x);
            ffma2(a1[0], xv1.x, xv1.y, g.y);
            ffma2(a1[1], xv1.z, xv1.w, g.y);
        }
    } else {
        for (int w = 0; w < WIN; w++) {
            int row = s + w - 5;
            if ((unsigned)row >= (unsigned)Sdim) continue;
            const float* xr = xq + (size_t)row * Edim;
            float4 xv0 = *(const float4*)(xr);
            float4 xv1 = *(const float4*)(xr + bst);
            float2 g = gates[grp * WIN + w];
            ffma2(a0[0], xv0.x, xv0.y, g.x);
            ffma2(a0[1], xv0.z, xv0.w, g.x);
            ffma2(a1[0], xv1.x, xv1.y, g.y);
            ffma2(a1[1], xv1.z, xv1.w, g.y);
        }
    }

    float4 o0, o1;
    o0.x = tanh_fast(a0[0].x); o0.y = tanh_fast(a0[0].y);
    o0.z = tanh_fast(a0[1].x); o0.w = tanh_fast(a0[1].y);
    o1.x = tanh_fast(a1[0].x); o1.y = tanh_fast(a1[0].y);
    o1.z = tanh_fast(a1[1].x); o1.w = tanh_fast(a1[1].y);
    float* op = out + ((size_t)(b0 + 2 * grp) * Sdim + s) * Edim + ex;
    *(float4*)(op)       = o0;
    *(float4*)(op + bst) = o1;
}

extern "C" void kernel_launch(void* const* d_in, const int* in_sizes, int n_in,
                              void* d_out, int out_size) {
    const float* x  = (const float*)d_in[0];
    const float* W  = (const float*)d_in[1];
    const float* bv = (const float*)d_in[2];
    float* out = (float*)d_out;

    winattn_kernel<<<2 * Sdim, NTH>>>(x, W, bv, out);
}